// round 12
// baseline (speedup 1.0000x reference)
#include <cuda_runtime.h>

#define N_QUBITS 7
#define DIM 128
#define DEPTH 2
#define NTHETA 14

typedef unsigned long long u64;

__device__ __forceinline__ u64 fma2(u64 a, u64 b, u64 c) {
    u64 d; asm("fma.rn.f32x2 %0, %1, %2, %3;" : "=l"(d) : "l"(a), "l"(b), "l"(c)); return d;
}
__device__ __forceinline__ u64 mul2(u64 a, u64 b) {
    u64 d; asm("mul.rn.f32x2 %0, %1, %2;" : "=l"(d) : "l"(a), "l"(b)); return d;
}
__device__ __forceinline__ u64 add2(u64 a, u64 b) {
    u64 d; asm("add.rn.f32x2 %0, %1, %2;" : "=l"(d) : "l"(a), "l"(b)); return d;
}
__device__ __forceinline__ u64 pack2(float lo, float hi) {
    u64 d; asm("mov.b64 %0, {%1, %2};" : "=l"(d) : "f"(lo), "f"(hi)); return d;
}

// TWO lanes per row (R12): lane = 2*r + p; thread holds v[32] (half the state),
// halving registers (158 -> ~100) to lift occupancy 10 -> 16+ warps/SM, which
// is the binding constraint (R11: occ 16.8%, no pipe >61%).
//
// Amp index bits: bit0 = h (packed lo/hi, q0), bits1..5 = j (q1..q5),
// bit6 = p (lane parity, q6). Qubit 6 rotates via shfl_xor(.,1) with the
// partner lane. Tangent form: (A,B) -> (A - t*B, B + t*A); global prod(cos)
// cancels in out = num / sum(probs).
//
// Proven elements kept: cp.async issued FIRST, __tanf prep hidden behind the
// in-flight loads, coefficients broadcast to registers (14 shuffles), depth
// loop FULLY unrolled so tn[] stays register-resident (R10 LDL lesson).
__global__ void __launch_bounds__(64, 8)
qnat_main_kernel(const float* __restrict__ embed,
                 const float* __restrict__ theta,
                 float* __restrict__ out,
                 int nrows) {
    __shared__ ulonglong2 tile[2][16][32];   // [warp][row][16B chunk, XOR-swizzled]

    const int l = threadIdx.x & 31;
    const int w = threadIdx.x >> 5;
    const int r = l >> 1;        // row within the 16-row batch
    const int p = l & 1;         // qubit-6 bit

    const long long rowbase = ((long long)blockIdx.x * 2 + w) * 16;
    if (rowbase >= nrows) return;   // whole-warp uniform exit
    const int valid = (int)(((long long)nrows - rowbase) < 16 ? (nrows - rowbase) : 16);

    // ---- 1) issue the DRAM fetch first (coalesced cp.async, XOR-16B swizzle) ----
    const float4* src = reinterpret_cast<const float4*>(embed + rowbase * DIM);
    #pragma unroll
    for (int it = 0; it < 16; it++) {
        if (it < valid) {
            unsigned dst = (unsigned)__cvta_generic_to_shared(&tile[w][it][l ^ it]);
            asm volatile("cp.async.cg.shared.global [%0], [%1], 16;"
                         :: "r"(dst), "l"(src + it * 32 + l) : "memory");
        }
    }
    asm volatile("cp.async.commit_group;" ::: "memory");

    // ---- 2) coefficients -> registers, hidden behind the in-flight loads ----
    float tv = 0.0f;
    if (l < NTHETA) tv = __tanf(theta[l] * 0.5f);
    float tn[NTHETA];
    #pragma unroll
    for (int i = 0; i < NTHETA; i++)
        tn[i] = __shfl_sync(0xffffffffu, tv, i);

    // ---- 3) wait for data ----
    asm volatile("cp.async.wait_group 0;" ::: "memory");
    __syncwarp();
    // NOTE: no early exit below — q6 shuffles need all 32 lanes. Tail rows
    // compute on stale smem (harmless) and are predicated at the store.

    // ---- own half-row into packed registers (swizzled LDS.128) ----
    // chunk c = p*16 + i holds amps 4c..4c+3 -> v[2i], v[2i+1]
    u64 v[32];
    #pragma unroll
    for (int i = 0; i < 16; i++) {
        ulonglong2 g = tile[w][r][(p * 16 + i) ^ r];
        v[2 * i]     = g.x;
        v[2 * i + 1] = g.y;
    }

    // ---- 2 depths of 7 tangent-form RY rotations + CZ between ----
    #pragma unroll
    for (int d = 0; d < DEPTH; d++) {
        const int t0 = d * N_QUBITS;
        // qubit 0 (lo/hi split): v' = v + (-t,+t)*(hi,lo)
        {
            float t = tn[t0];
            u64 np = pack2(-t, t);
            #pragma unroll
            for (int j = 0; j < 32; j++) {
                u64 sw = (v[j] << 32) | (v[j] >> 32);
                v[j] = fma2(np, sw, v[j]);
            }
        }
        // qubits 1..5: intra-thread pairs (v[j], v[j+m])
        #pragma unroll
        for (int q = 1; q < 6; q++) {
            float t = tn[t0 + q];
            u64 tt = pack2(t, t);
            u64 nt = pack2(-t, -t);
            const int m = 1 << (q - 1);
            #pragma unroll
            for (int j = 0; j < 32; j++) {
                if (!(j & m)) {
                    u64 A = v[j];
                    v[j]     = fma2(nt, v[j + m], A);
                    v[j + m] = fma2(tt, A, v[j + m]);
                }
            }
        }
        // qubit 6 (lane parity): exchange with partner lane
        // p=0 holds bit6=0: v' = v - t*partner ; p=1: v' = v + t*partner
        {
            float t = tn[t0 + 6];
            u64 ts = p ? pack2(t, t) : pack2(-t, -t);
            #pragma unroll
            for (int j = 0; j < 32; j++) {
                u64 b = __shfl_xor_sync(0xffffffffu, v[j], 1);
                v[j] = fma2(ts, b, v[j]);
            }
        }
        // CZ after depth 0 only: parity = h*j0 + j0j1+j1j2+j2j3+j3j4 + j4*p
        if (d == 0) {
            #pragma unroll
            for (int j = 0; j < 32; j++) {
                int base = __popc(j & (j >> 1) & 0xF) & 1;
                int pj = base ^ (((j >> 4) & 1) & p);
                int ph = pj ^ (j & 1);
                u64 mask = ((u64)pj << 31) | ((u64)ph << 63);
                v[j] ^= mask;
            }
        }
    }

    // ---- probabilities (packed squares) ----
    #pragma unroll
    for (int j = 0; j < 32; j++) v[j] = mul2(v[j], v[j]);

    // ---- in-place packed subset-sum tree over the 5 bits of j ----
    #pragma unroll
    for (int k = 0; k < 5; k++) {
        const int m = 1 << k;
        #pragma unroll
        for (int base = 0; base < 32; base += 2 * m) {
            v[base] = add2(v[base], v[base + m]);
            #pragma unroll
            for (int t = 0; t < k; t++)
                v[base + (1 << t)] = add2(v[base + (1 << t)], v[base + m + (1 << t)]);
        }
    }

    // ---- finalize: combine the two half-rows (7 scalar shuffles) ----
    float lo = __uint_as_float((unsigned)v[0]);
    float hi = __uint_as_float((unsigned)(v[0] >> 32));
    float St = lo + hi;          // this half's total
    float d0 = lo - hi;          // q0-signed partial
    float g1 = __uint_as_float((unsigned)v[1])  + __uint_as_float((unsigned)(v[1]  >> 32));
    float g2 = __uint_as_float((unsigned)v[2])  + __uint_as_float((unsigned)(v[2]  >> 32));
    float g3 = __uint_as_float((unsigned)v[4])  + __uint_as_float((unsigned)(v[4]  >> 32));
    float g4 = __uint_as_float((unsigned)v[8])  + __uint_as_float((unsigned)(v[8]  >> 32));
    float g5 = __uint_as_float((unsigned)v[16]) + __uint_as_float((unsigned)(v[16] >> 32));

    float Sp  = __shfl_xor_sync(0xffffffffu, St, 1);
    float d0p = __shfl_xor_sync(0xffffffffu, d0, 1);
    float g1p = __shfl_xor_sync(0xffffffffu, g1, 1);
    float g2p = __shfl_xor_sync(0xffffffffu, g2, 1);
    float g3p = __shfl_xor_sync(0xffffffffu, g3, 1);
    float g4p = __shfl_xor_sync(0xffffffffu, g4, 1);
    float g5p = __shfl_xor_sync(0xffffffffu, g5, 1);

    float S   = St + Sp;
    float inv = __fdividef(1.0f, S);

    if (r < valid) {
        float* o = out + (rowbase + r) * N_QUBITS;
        if (p == 0) {
            o[0] = (d0 + d0p) * inv;
            o[1] = fmaf(-2.0f * (g1 + g1p), inv, 1.0f);
            o[2] = fmaf(-2.0f * (g2 + g2p), inv, 1.0f);
            o[3] = fmaf(-2.0f * (g3 + g3p), inv, 1.0f);
        } else {
            o[4] = fmaf(-2.0f * (g4 + g4p), inv, 1.0f);
            o[5] = fmaf(-2.0f * (g5 + g5p), inv, 1.0f);
            o[6] = (Sp - St) * inv;   // sum(p=0) - sum(p=1)
        }
    }
}

extern "C" void kernel_launch(void* const* d_in, const int* in_sizes, int n_in,
                              void* d_out, int out_size) {
    const float* embed = (const float*)d_in[0];
    const float* theta = (const float*)d_in[1];
    float* out = (float*)d_out;

    static bool attr_set = false;
    if (!attr_set) {
        cudaFuncSetAttribute(qnat_main_kernel,
                             cudaFuncAttributePreferredSharedMemoryCarveout, 100);
        attr_set = true;
    }

    int nrows = in_sizes[0] / DIM;
    int nbatches = (nrows + 15) / 16;      // 16 rows per warp
    int grid = (nbatches + 1) / 2;         // 2 warps (64 threads) per block

    qnat_main_kernel<<<grid, 64>>>(embed, theta, out, nrows);
}